// round 11
// baseline (speedup 1.0000x reference)
#include <cuda_runtime.h>
#include <math.h>

#define BB 4
#define SS 2048
#define HH 512
#define NROWS (BB * SS)                 // 8192
#define QKV_LIM (NROWS * HH)            // 4,194,304  (also the output float count)
#define W_LIM   (HH * HH)               // 262,144
#define CH      256                     // j-chunk width
#define NCH     (SS / CH)               // 8
#define QB_LIM  (SS * HH)               // per-batch scratch: 1,048,576 (4 MB)
#define SB_LIM  (SS * CH)               // per-batch S chunk:   524,288 (2 MB)
// log2(31/32)
#define LOG2_GAMMA (-0.045803689613124795f)

__device__ __forceinline__ int cl(int idx, int lim) { return min(idx, lim - 1); }

// ---------------- scratch: 22 MB total, batch-local ----------
__device__ float g_qr[QB_LIM];
__device__ float g_qi[QB_LIM];
__device__ float g_kr[QB_LIM];
__device__ float g_ki[QB_LIM];
__device__ float g_v [QB_LIM];
__device__ float g_sr[SB_LIM];          // real scores only — output is Re(out)

// ============================================================================
// Kernel 1: QKV projection + rotation, one batch. Tile 128(m) x 64(n), K=512.
// 256 threads (tx=tid&15, ty=tid>>4), micro 8x4. Scalar loads only.
// z: 0=Q -> (qr,qi), 1=K -> (kr,ki), 2=V -> v.   Scratch is batch-local.
// ============================================================================
__global__ __launch_bounds__(256) void qkv_b_kernel(
    const float* __restrict__ x,
    const float* __restrict__ Wq,
    const float* __restrict__ Wk,
    const float* __restrict__ Wv,
    const float* __restrict__ theta,
    int b, int x_lim, int w_lim, int th_lim)
{
    __shared__ float As[16][129];   // As[k][m]
    __shared__ float Bs[16][65];    // Bs[k][n]

    const int z  = blockIdx.z;
    const float* __restrict__ W = (z == 0) ? Wq : (z == 1) ? Wk : Wv;
    const int n0 = blockIdx.x * 64;
    const int m0 = blockIdx.y * 128;
    const int tid = threadIdx.x;
    const int tx = tid & 15;
    const int ty = tid >> 4;

    float acc[8][4];
#pragma unroll
    for (int i = 0; i < 8; i++)
#pragma unroll
        for (int j = 0; j < 4; j++) acc[i][j] = 0.f;

    for (int k0 = 0; k0 < HH; k0 += 16) {
        __syncthreads();
        for (int l = tid; l < 128 * 16; l += 256) {
            int row = l >> 4, k = l & 15;
            As[k][row] = x[cl((b * SS + m0 + row) * HH + k0 + k, x_lim)];
        }
        for (int l = tid; l < 16 * 64; l += 256) {
            int k = l >> 6, n = l & 63;
            Bs[k][n] = W[cl((k0 + k) * HH + n0 + n, w_lim)];
        }
        __syncthreads();
#pragma unroll
        for (int kk = 0; kk < 16; kk++) {
            float a[8], bv[4];
#pragma unroll
            for (int i = 0; i < 8; i++) a[i] = As[kk][ty * 8 + i];
#pragma unroll
            for (int j = 0; j < 4; j++) bv[j] = Bs[kk][tx * 4 + j];
#pragma unroll
            for (int i = 0; i < 8; i++)
#pragma unroll
                for (int j = 0; j < 4; j++)
                    acc[i][j] = fmaf(a[i], bv[j], acc[i][j]);
        }
    }

#pragma unroll
    for (int i = 0; i < 8; i++) {
        const int srow = m0 + ty * 8 + i;          // 0..2047 within batch
        const float nf = (float)(srow + 1);
#pragma unroll
        for (int j = 0; j < 4; j++) {
            const int n = n0 + tx * 4 + j;          // 0..511
            const int idx = cl(srow * HH + n, QB_LIM);
            const float v = acc[i][j];
            if (z == 2) {
                g_v[idx] = v;
            } else {
                float sn, cs;
                sincosf(nf * theta[cl(n, th_lim)], &sn, &cs);
                if (z == 0) { g_qr[idx] = v * cs; g_qi[idx] =  v * sn; }
                else        { g_kr[idx] = v * cs; g_ki[idx] = -v * sn; }
            }
        }
    }
}

// ============================================================================
// Kernel 2: REAL scores for one batch, one j-chunk. Tile 128(i)x64(j), K=512.
// Sr = qr*kr^T - qi*ki^T, then decay gamma^(i-j) (0 above diagonal).
// (Si dropped: the harness output is the real part only.)
// ============================================================================
__global__ __launch_bounds__(256) void scores_b_kernel(int jc)
{
    const int j0l = blockIdx.x * 64;
    const int j0g = jc * CH + j0l;
    const int i0  = blockIdx.y * 128;
    if (j0g > i0 + 127) return;                    // fully above diagonal

    __shared__ float Aqr[16][129];
    __shared__ float Aqi[16][129];
    __shared__ float Bkr[16][65];
    __shared__ float Bki[16][65];

    const int tid = threadIdx.x;
    const int tx = tid & 15;
    const int ty = tid >> 4;

    float sr[8][4];
#pragma unroll
    for (int i = 0; i < 8; i++)
#pragma unroll
        for (int j = 0; j < 4; j++) sr[i][j] = 0.f;

    for (int k0 = 0; k0 < HH; k0 += 16) {
        __syncthreads();
        for (int l = tid; l < 128 * 16; l += 256) {
            int row = l >> 4, k = l & 15;
            int off = cl((i0 + row) * HH + k0 + k, QB_LIM);
            Aqr[k][row] = g_qr[off];
            Aqi[k][row] = g_qi[off];
        }
        for (int l = tid; l < 16 * 64; l += 256) {
            int k = l >> 6, j = l & 63;
            int off = cl((j0g + j) * HH + k0 + k, QB_LIM);
            Bkr[k][j] = g_kr[off];
            Bki[k][j] = g_ki[off];
        }
        __syncthreads();
#pragma unroll
        for (int kk = 0; kk < 16; kk++) {
            float ar[8], ai[8], br[4], bi[4];
#pragma unroll
            for (int i = 0; i < 8; i++) { ar[i] = Aqr[kk][ty * 8 + i]; ai[i] = Aqi[kk][ty * 8 + i]; }
#pragma unroll
            for (int j = 0; j < 4; j++) { br[j] = Bkr[kk][tx * 4 + j]; bi[j] = Bki[kk][tx * 4 + j]; }
#pragma unroll
            for (int i = 0; i < 8; i++)
#pragma unroll
                for (int j = 0; j < 4; j++) {
                    sr[i][j] = fmaf(ar[i],  br[j], sr[i][j]);
                    sr[i][j] = fmaf(-ai[i], bi[j], sr[i][j]);
                }
        }
    }

#pragma unroll
    for (int i = 0; i < 8; i++) {
        const int gi = i0 + ty * 8 + i;
#pragma unroll
        for (int j = 0; j < 4; j++) {
            const int gj = j0g + tx * 4 + j;
            const int d  = gi - gj;
            const float w = (d < 0) ? 0.f : exp2f((float)d * LOG2_GAMMA);
            g_sr[cl(gi * CH + j0l + tx * 4 + j, SB_LIM)] = sr[i][j] * w;
        }
    }
}

// ============================================================================
// Kernel 3: O(+)= Sr_chunk @ V_chunk, one batch, one j-chunk. Tile 128(i)x64(h).
// jc==0 initializes O (never reads poison). Output: REAL PART ONLY, float32
// [B,S,H] c-order, never beyond out_limf floats.
// ============================================================================
__global__ __launch_bounds__(256) void out_b_kernel(float* __restrict__ out,
                                                    int out_limf, int b, int jc)
{
    const int i0 = blockIdx.y * 128;
    if (jc > 0 && i0 + 128 <= jc * CH) return;     // no causal work this chunk
    const int h0 = blockIdx.x * 64;

    __shared__ float Asr[16][129];
    __shared__ float Bv [16][65];

    const int tid = threadIdx.x;
    const int tx = tid & 15;
    const int ty = tid >> 4;

    float orr[8][4];
#pragma unroll
    for (int i = 0; i < 8; i++)
#pragma unroll
        for (int j = 0; j < 4; j++) orr[i][j] = 0.f;

    int jend = i0 + 128 - jc * CH;                 // causal extent in chunk
    if (jend > CH) jend = CH;                      // (>0 here; multiple of 16)

    for (int j0l = 0; j0l < jend; j0l += 16) {
        __syncthreads();
        for (int l = tid; l < 128 * 16; l += 256) {
            int row = l >> 4, jj = l & 15;
            Asr[jj][row] = g_sr[cl((i0 + row) * CH + j0l + jj, SB_LIM)];
        }
        for (int l = tid; l < 16 * 64; l += 256) {
            int jj = l >> 6, h = l & 63;
            Bv[jj][h] = g_v[cl((jc * CH + j0l + jj) * HH + h0 + h, QB_LIM)];
        }
        __syncthreads();
#pragma unroll
        for (int kk = 0; kk < 16; kk++) {
            float srv[8], vv[4];
#pragma unroll
            for (int i = 0; i < 8; i++) srv[i] = Asr[kk][ty * 8 + i];
#pragma unroll
            for (int j = 0; j < 4; j++) vv[j] = Bv[kk][tx * 4 + j];
#pragma unroll
            for (int i = 0; i < 8; i++)
#pragma unroll
                for (int j = 0; j < 4; j++)
                    orr[i][j] = fmaf(srv[i], vv[j], orr[i][j]);
        }
    }

#pragma unroll
    for (int i = 0; i < 8; i++) {
        const int gi = i0 + ty * 8 + i;
#pragma unroll
        for (int j = 0; j < 4; j++) {
            const int gh = h0 + tx * 4 + j;
            const int oidx = cl((b * SS + gi) * HH + gh, out_limf);
            float v = orr[i][j];
            if (jc > 0) v += out[oidx];            // accumulate across chunks
            out[oidx] = v;
        }
    }
}

// ============================================================================
// Binding (rank by size, order/unit-independent, null fallbacks) + runtime
// extents. Output: float32 real part, extent min(out_size, QKV_LIM) floats
// (R8 empirically confirmed 16 MB of writes is in-bounds).
// ============================================================================
extern "C" void kernel_launch(void* const* d_in, const int* in_sizes, int n_in,
                              void* d_out, int out_size)
{
    long long smax = -1, smin = 0x7fffffffffffLL;
    for (int i = 0; i < n_in; i++) {
        long long s = (long long)in_sizes[i];
        if (s > smax) smax = s;
        if (s < smin) smin = s;
    }

    const float* x  = nullptr;
    const float* th = nullptr;
    const float* w[3] = {nullptr, nullptr, nullptr};
    long long xs = QKV_LIM, ths = HH, ws = W_LIM;
    int nw = 0;
    int x_pos = -1, th_pos = 1 << 30;

    for (int i = 0; i < n_in; i++) {
        long long s = (long long)in_sizes[i];
        if (s == smax && x == nullptr)       { x  = (const float*)d_in[i]; xs = s;  x_pos  = i; }
        else if (s == smin && th == nullptr) { th = (const float*)d_in[i]; ths = s; th_pos = i; }
        else if (nw < 3)                     { ws = s; w[nw++] = (const float*)d_in[i]; }
    }

    const float* safe = (const float*)d_in[0];
    if (!x)  x  = safe;
    if (!th) th = safe;
    for (int i = 0; i < 3; i++) if (!w[i]) w[i] = safe;

    const float *wq, *wk, *wv;
    if (x_pos < th_pos) {            // dict order: x, wq, wk, wv, theta
        wq = w[0]; wk = w[1]; wv = w[2];
    } else {                         // alphabetical: theta, wk, wq, wv, x
        wk = w[0]; wq = w[1]; wv = w[2];
    }

    int x_lim  = (int)((xs  < (long long)QKV_LIM) ? xs  : QKV_LIM);
    int w_lim  = (int)((ws  < (long long)W_LIM)   ? ws  : W_LIM);
    int th_lim = (int)((ths < (long long)HH)      ? ths : HH);
    if (x_lim < 1)  x_lim = 1;
    if (w_lim < 1)  w_lim = 1;
    if (th_lim < 1) th_lim = 1;

    // Output: real part only, float32, [B,S,H] = QKV_LIM floats.
    long long o = (long long)out_size;
    long long out_limf = (o < (long long)QKV_LIM) ? o : (long long)QKV_LIM;
    if (out_limf < 1) out_limf = 1;

    for (int b = 0; b < BB; b++) {
        qkv_b_kernel<<<dim3(HH / 64, SS / 128, 3), 256>>>(x, wq, wk, wv, th,
                                                          b, x_lim, w_lim, th_lim);
        for (int jc = 0; jc < NCH; jc++) {
            scores_b_kernel<<<dim3(CH / 64, SS / 128), 256>>>(jc);
            out_b_kernel<<<dim3(HH / 64, SS / 128), 256>>>((float*)d_out,
                                                           (int)out_limf, b, jc);
        }
    }
}

// round 12
// speedup vs baseline: 5.2056x; 5.2056x over previous
#include <cuda_runtime.h>
#include <math.h>

#define BB 4
#define SS 2048
#define HH 512
#define NROWS (BB * SS)                 // 8192
#define QKV_LIM (NROWS * HH)            // 4,194,304 (= output float count)
#define W_LIM   (HH * HH)               // 262,144
#define S_LIM   (BB * SS * SS)          // 16,777,216 (64 MB)
// log2(31/32)
#define LOG2_GAMMA (-0.045803689613124795f)

__device__ __forceinline__ int clamp4(int idx, int lim) {
    return min(idx, lim - 4);           // lim multiple of 4: keeps float4 alignment
}
__device__ __forceinline__ int clamp1(int idx, int lim) {
    return min(idx, lim - 1);
}

// ---------------- scratch (statics exonerated; 144 MB total) ----------
__device__ __align__(16) float g_qr[QKV_LIM];
__device__ __align__(16) float g_qi[QKV_LIM];
__device__ __align__(16) float g_kr[QKV_LIM];
__device__ __align__(16) float g_ki[QKV_LIM];
__device__ __align__(16) float g_v [QKV_LIM];
__device__ __align__(16) float g_sr[S_LIM];     // real scores only

// ============================================================================
// Kernel 1: QKV projection + rotation epilogue, all batches.
// GEMM M=8192, N=512, K=512. CTA tile 128x128, 256 threads, 8x8 micro, float4.
// blockIdx.z: 0=Q -> (qr,qi), 1=K -> (kr,ki), 2=V -> v.  Grid: (4, 64, 3).
// ============================================================================
__global__ __launch_bounds__(256) void qkv_kernel(
    const float* __restrict__ x,
    const float* __restrict__ Wq,
    const float* __restrict__ Wk,
    const float* __restrict__ Wv,
    const float* __restrict__ theta,
    int x_lim, int w_lim, int th_lim)
{
    __shared__ float As[8][128];
    __shared__ float Bs[8][128];

    const int z = blockIdx.z;
    const float* __restrict__ W = (z == 0) ? Wq : (z == 1) ? Wk : Wv;
    const int m0 = blockIdx.y * 128;
    const int n0 = blockIdx.x * 128;
    const int tid = threadIdx.x;
    const int tx = tid & 15;
    const int ty = tid >> 4;

    const int arow = tid >> 1;            // 0..127
    const int acol = (tid & 1) * 4;       // 0 or 4
    const int brow = tid >> 5;            // 0..7
    const int bcol = (tid & 31) * 4;      // 0..124

    float acc[8][8];
#pragma unroll
    for (int i = 0; i < 8; i++)
#pragma unroll
        for (int j = 0; j < 8; j++) acc[i][j] = 0.f;

    for (int k0 = 0; k0 < HH; k0 += 8) {
        float4 av = *(const float4*)&x[clamp4((m0 + arow) * HH + (k0 + acol), x_lim)];
        float4 bv = *(const float4*)&W[clamp4((k0 + brow) * HH + (n0 + bcol), w_lim)];
        __syncthreads();
        As[acol + 0][arow] = av.x;
        As[acol + 1][arow] = av.y;
        As[acol + 2][arow] = av.z;
        As[acol + 3][arow] = av.w;
        *(float4*)&Bs[brow][bcol] = bv;
        __syncthreads();
#pragma unroll
        for (int kk = 0; kk < 8; kk++) {
            float a[8], b[8];
            *(float4*)&a[0] = *(const float4*)&As[kk][ty * 4];
            *(float4*)&a[4] = *(const float4*)&As[kk][64 + ty * 4];
            *(float4*)&b[0] = *(const float4*)&Bs[kk][tx * 4];
            *(float4*)&b[4] = *(const float4*)&Bs[kk][64 + tx * 4];
#pragma unroll
            for (int i = 0; i < 8; i++)
#pragma unroll
                for (int j = 0; j < 8; j++)
                    acc[i][j] = fmaf(a[i], b[j], acc[i][j]);
        }
    }

    // epilogue: rotation by exp(+/- i (s+1) theta[n])
#pragma unroll
    for (int i = 0; i < 8; i++) {
        const int m = m0 + ((i < 4) ? (ty * 4 + i) : (64 + ty * 4 + i - 4));
        const int s = m & (SS - 1);
        const float nf = (float)(s + 1);
#pragma unroll
        for (int j = 0; j < 8; j++) {
            const int n = n0 + ((j < 4) ? (tx * 4 + j) : (64 + tx * 4 + j - 4));
            const float v = acc[i][j];
            const int idx = m * HH + n;          // < QKV_LIM by construction
            if (z == 2) {
                g_v[idx] = v;
            } else {
                float sn, cs;
                sincosf(nf * theta[clamp1(n, th_lim)], &sn, &cs);
                if (z == 0) { g_qr[idx] = v * cs; g_qi[idx] =  v * sn; }
                else        { g_kr[idx] = v * cs; g_ki[idx] = -v * sn; }
            }
        }
    }
}

// ============================================================================
// Kernel 2: REAL scores, all batches. Sr = qr*kr^T - qi*ki^T, then decay
// gamma^(i-j) (0 above diagonal). CTA tile 128(i) x 128(j), K=H=512,
// 256 threads, 8x8 micro. Grid: (16, 16, 4); above-diagonal tiles exit.
// ============================================================================
__global__ __launch_bounds__(256) void scores_kernel()
{
    const int j0 = blockIdx.x * 128;
    const int i0 = blockIdx.y * 128;
    if (j0 > i0 + 127) return;              // fully above diagonal
    const int b = blockIdx.z;
    const int rbase = b * SS;

    __shared__ float Aqr[8][128];
    __shared__ float Aqi[8][128];
    __shared__ float Bkr[8][128];
    __shared__ float Bki[8][128];

    const int tid = threadIdx.x;
    const int tx = tid & 15;
    const int ty = tid >> 4;
    const int arow = tid >> 1;              // 0..127
    const int acol = (tid & 1) * 4;         // 0 or 4

    float sr[8][8];
#pragma unroll
    for (int i = 0; i < 8; i++)
#pragma unroll
        for (int j = 0; j < 8; j++) sr[i][j] = 0.f;

    for (int k0 = 0; k0 < HH; k0 += 8) {
        const int aoff = (rbase + i0 + arow) * HH + k0 + acol;
        const int boff = (rbase + j0 + arow) * HH + k0 + acol;
        float4 vqr = *(const float4*)&g_qr[aoff];
        float4 vqi = *(const float4*)&g_qi[aoff];
        float4 vkr = *(const float4*)&g_kr[boff];
        float4 vki = *(const float4*)&g_ki[boff];
        __syncthreads();
        Aqr[acol + 0][arow] = vqr.x;
        Aqr[acol + 1][arow] = vqr.y;
        Aqr[acol + 2][arow] = vqr.z;
        Aqr[acol + 3][arow] = vqr.w;
        Aqi[acol + 0][arow] = vqi.x;
        Aqi[acol + 1][arow] = vqi.y;
        Aqi[acol + 2][arow] = vqi.z;
        Aqi[acol + 3][arow] = vqi.w;
        Bkr[acol + 0][arow] = vkr.x;
        Bkr[acol + 1][arow] = vkr.y;
        Bkr[acol + 2][arow] = vkr.z;
        Bkr[acol + 3][arow] = vkr.w;
        Bki[acol + 0][arow] = vki.x;
        Bki[acol + 1][arow] = vki.y;
        Bki[acol + 2][arow] = vki.z;
        Bki[acol + 3][arow] = vki.w;
        __syncthreads();
#pragma unroll
        for (int kk = 0; kk < 8; kk++) {
            float ar[8], ai[8], br[8], bi[8];
            *(float4*)&ar[0] = *(const float4*)&Aqr[kk][ty * 4];
            *(float4*)&ar[4] = *(const float4*)&Aqr[kk][64 + ty * 4];
            *(float4*)&ai[0] = *(const float4*)&Aqi[kk][ty * 4];
            *(float4*)&ai[4] = *(const float4*)&Aqi[kk][64 + ty * 4];
            *(float4*)&br[0] = *(const float4*)&Bkr[kk][tx * 4];
            *(float4*)&br[4] = *(const float4*)&Bkr[kk][64 + tx * 4];
            *(float4*)&bi[0] = *(const float4*)&Bki[kk][tx * 4];
            *(float4*)&bi[4] = *(const float4*)&Bki[kk][64 + tx * 4];
#pragma unroll
            for (int i = 0; i < 8; i++)
#pragma unroll
                for (int j = 0; j < 8; j++) {
                    sr[i][j] = fmaf(ar[i],  br[j], sr[i][j]);
                    sr[i][j] = fmaf(-ai[i], bi[j], sr[i][j]);
                }
        }
    }

    const int sbase = b * SS * SS;
#pragma unroll
    for (int i = 0; i < 8; i++) {
        const int gi = i0 + ((i < 4) ? (ty * 4 + i) : (64 + ty * 4 + i - 4));
#pragma unroll
        for (int half = 0; half < 2; half++) {
            const int gjbase = j0 + ((half == 0) ? tx * 4 : 64 + tx * 4);
            float4 vr;
            float* pr = &vr.x;
#pragma unroll
            for (int q = 0; q < 4; q++) {
                const int d = gi - (gjbase + q);
                const float w = (d < 0) ? 0.f : exp2f((float)d * LOG2_GAMMA);
                pr[q] = sr[i][half * 4 + q] * w;
            }
            *(float4*)&g_sr[sbase + gi * SS + gjbase] = vr;
        }
    }
}

// ============================================================================
// Kernel 3: O = Sr @ V (triangular K-range: j < i0+128), all batches.
// CTA tile 128(i) x 64(h), 256 threads, 8x4 micro. Grid: (8, 16, 4).
// Output: REAL PART ONLY, float32 [B,S,H].
// ============================================================================
__global__ __launch_bounds__(256) void out_kernel(float* __restrict__ out,
                                                  int out_limf)
{
    const int h0 = blockIdx.x * 64;
    const int i0 = blockIdx.y * 128;
    const int b  = blockIdx.z;
    const int sbase = b * SS * SS;
    const int rbase = b * SS;

    __shared__ float Asr[8][128];
    __shared__ float Bv [8][64];

    const int tid = threadIdx.x;
    const int tx = tid & 15;
    const int ty = tid >> 4;

    const int arow = tid >> 1;
    const int acol = (tid & 1) * 4;
    const int brow = tid >> 4;            // valid for tid < 128: 0..7
    const int bcol = (tid & 15) * 4;

    float orr[8][4];
#pragma unroll
    for (int i = 0; i < 8; i++)
#pragma unroll
        for (int j = 0; j < 4; j++) orr[i][j] = 0.f;

    const int jend = i0 + 128;            // causal extent for this row tile
    for (int j0 = 0; j0 < jend; j0 += 8) {
        float4 asr = *(const float4*)&g_sr[sbase + (i0 + arow) * SS + j0 + acol];
        float4 bv;
        if (tid < 128)
            bv = *(const float4*)&g_v[(rbase + j0 + brow) * HH + h0 + bcol];
        __syncthreads();
        Asr[acol + 0][arow] = asr.x;
        Asr[acol + 1][arow] = asr.y;
        Asr[acol + 2][arow] = asr.z;
        Asr[acol + 3][arow] = asr.w;
        if (tid < 128)
            *(float4*)&Bv[brow][bcol] = bv;
        __syncthreads();
#pragma unroll
        for (int kk = 0; kk < 8; kk++) {
            float srv[8], vv[4];
            *(float4*)&srv[0] = *(const float4*)&Asr[kk][ty * 4];
            *(float4*)&srv[4] = *(const float4*)&Asr[kk][64 + ty * 4];
            *(float4*)&vv[0]  = *(const float4*)&Bv[kk][tx * 4];
#pragma unroll
            for (int i = 0; i < 8; i++)
#pragma unroll
                for (int j = 0; j < 4; j++)
                    orr[i][j] = fmaf(srv[i], vv[j], orr[i][j]);
        }
    }

#pragma unroll
    for (int i = 0; i < 8; i++) {
        const int gi = i0 + ((i < 4) ? (ty * 4 + i) : (64 + ty * 4 + i - 4));
#pragma unroll
        for (int j = 0; j < 4; j++) {
            const int gh = h0 + tx * 4 + j;
            out[clamp1((rbase + gi) * HH + gh, out_limf)] = orr[i][j];
        }
    }
}

// ============================================================================
// Binding (rank by size, order/unit-independent, null fallbacks) + runtime
// extents. Output: float32 real part, extent min(out_size, QKV_LIM) floats.
// ============================================================================
extern "C" void kernel_launch(void* const* d_in, const int* in_sizes, int n_in,
                              void* d_out, int out_size)
{
    long long smax = -1, smin = 0x7fffffffffffLL;
    for (int i = 0; i < n_in; i++) {
        long long s = (long long)in_sizes[i];
        if (s > smax) smax = s;
        if (s < smin) smin = s;
    }

    const float* x  = nullptr;
    const float* th = nullptr;
    const float* w[3] = {nullptr, nullptr, nullptr};
    long long xs = QKV_LIM, ths = HH, ws = W_LIM;
    int nw = 0;
    int x_pos = -1, th_pos = 1 << 30;

    for (int i = 0; i < n_in; i++) {
        long long s = (long long)in_sizes[i];
        if (s == smax && x == nullptr)       { x  = (const float*)d_in[i]; xs = s;  x_pos  = i; }
        else if (s == smin && th == nullptr) { th = (const float*)d_in[i]; ths = s; th_pos = i; }
        else if (nw < 3)                     { ws = s; w[nw++] = (const float*)d_in[i]; }
    }

    const float* safe = (const float*)d_in[0];
    if (!x)  x  = safe;
    if (!th) th = safe;
    for (int i = 0; i < 3; i++) if (!w[i]) w[i] = safe;

    const float *wq, *wk, *wv;
    if (x_pos < th_pos) {            // dict order: x, wq, wk, wv, theta
        wq = w[0]; wk = w[1]; wv = w[2];
    } else {                         // alphabetical: theta, wk, wq, wv, x
        wk = w[0]; wq = w[1]; wv = w[2];
    }

    int x_lim  = (int)((xs  < (long long)QKV_LIM) ? xs  : QKV_LIM);
    int w_lim  = (int)((ws  < (long long)W_LIM)   ? ws  : W_LIM);
    int th_lim = (int)((ths < (long long)HH)      ? ths : HH);
    if (x_lim < 4)  x_lim = 4;
    if (w_lim < 4)  w_lim = 4;
    if (th_lim < 1) th_lim = 1;

    long long o = (long long)out_size;
    long long out_limf = (o < (long long)QKV_LIM) ? o : (long long)QKV_LIM;
    if (out_limf < 1) out_limf = 1;

    qkv_kernel<<<dim3(HH / 128, NROWS / 128, 3), 256>>>(x, wq, wk, wv, th,
                                                        x_lim, w_lim, th_lim);
    scores_kernel<<<dim3(SS / 128, SS / 128, BB), 256>>>();
    out_kernel<<<dim3(HH / 64, SS / 128, BB), 256>>>((float*)d_out, (int)out_limf);
}

// round 14
// speedup vs baseline: 7.9865x; 1.5342x over previous
#include <cuda_runtime.h>
#include <cuda_bf16.h>
#include <cstdint>
#include <math.h>

#define BB 4
#define SS 2048
#define HH 512
#define NROWS (BB * SS)                 // 8192
#define QKV_LIM (NROWS * HH)            // 4,194,304 (= output float count)
#define W_LIM   (HH * HH)               // 262,144
#define S_LIM   (BB * SS * SS)          // 16,777,216
// log2(31/32)
#define LOG2_GAMMA (-0.045803689613124795f)

__device__ __forceinline__ int clamp4(int idx, int lim) { return min(idx, lim - 4); }
__device__ __forceinline__ int clamp1(int idx, int lim) { return min(idx, lim - 1); }

// ---------------- scratch: split-bf16 planes (144 MB total) ----------
__device__ __align__(16) __nv_bfloat16 g_qr_h[QKV_LIM], g_qr_l[QKV_LIM];
__device__ __align__(16) __nv_bfloat16 g_qi_h[QKV_LIM], g_qi_l[QKV_LIM];
__device__ __align__(16) __nv_bfloat16 g_kr_h[QKV_LIM], g_kr_l[QKV_LIM];
__device__ __align__(16) __nv_bfloat16 g_ks_h[QKV_LIM], g_ks_l[QKV_LIM]; // +v*sin (sign pre-flipped)
__device__ __align__(16) __nv_bfloat16 g_v_h [QKV_LIM], g_v_l [QKV_LIM];
__device__ __align__(16) __nv_bfloat16 g_sr_h[S_LIM],  g_sr_l[S_LIM];

// ---------------- mma helpers ----------------
__device__ __forceinline__ uint32_t s2u(const void* p) {
    return (uint32_t)__cvta_generic_to_shared(p);
}
__device__ __forceinline__ void ldsm_x4(uint32_t& r0, uint32_t& r1, uint32_t& r2, uint32_t& r3,
                                        uint32_t addr) {
    asm volatile("ldmatrix.sync.aligned.m8n8.x4.shared.b16 {%0,%1,%2,%3}, [%4];"
                 : "=r"(r0), "=r"(r1), "=r"(r2), "=r"(r3) : "r"(addr));
}
__device__ __forceinline__ void ldsm_x4_t(uint32_t& r0, uint32_t& r1, uint32_t& r2, uint32_t& r3,
                                          uint32_t addr) {
    asm volatile("ldmatrix.sync.aligned.m8n8.x4.trans.shared.b16 {%0,%1,%2,%3}, [%4];"
                 : "=r"(r0), "=r"(r1), "=r"(r2), "=r"(r3) : "r"(addr));
}
__device__ __forceinline__ void mma16816(float* c, const uint32_t* a, const uint32_t* b) {
    asm volatile("mma.sync.aligned.m16n8k16.row.col.f32.bf16.bf16.f32 "
                 "{%0,%1,%2,%3}, {%4,%5,%6,%7}, {%8,%9}, {%0,%1,%2,%3};"
                 : "+f"(c[0]), "+f"(c[1]), "+f"(c[2]), "+f"(c[3])
                 : "r"(a[0]), "r"(a[1]), "r"(a[2]), "r"(a[3]), "r"(b[0]), "r"(b[1]));
}
__device__ __forceinline__ void store_split2(__nv_bfloat16* hp, __nv_bfloat16* lp,
                                             int idx, float x0, float x1) {
    __nv_bfloat16 h0 = __float2bfloat16(x0);
    __nv_bfloat16 l0 = __float2bfloat16(x0 - __bfloat162float(h0));
    __nv_bfloat16 h1 = __float2bfloat16(x1);
    __nv_bfloat16 l1 = __float2bfloat16(x1 - __bfloat162float(h1));
    __nv_bfloat162 H; H.x = h0; H.y = h1;
    __nv_bfloat162 L; L.x = l0; L.y = l1;
    *(__nv_bfloat162*)&hp[idx] = H;
    *(__nv_bfloat162*)&lp[idx] = L;
}

// ============================================================================
// Kernel 1: QKV projection (fp32 FFMA) + rotation epilogue writing split-bf16
// planes. GEMM M=8192, N=512, K=512; tile 128x128, 256 thr, 8x8 micro, float4.
// z: 0=Q -> (qr,qi), 1=K -> (kr, ks=+v*sin), 2=V.  Grid (4, 64, 3).
// ============================================================================
__global__ __launch_bounds__(256) void qkv_kernel(
    const float* __restrict__ x,
    const float* __restrict__ Wq,
    const float* __restrict__ Wk,
    const float* __restrict__ Wv,
    const float* __restrict__ theta,
    int x_lim, int w_lim, int th_lim)
{
    __shared__ float As[8][128];
    __shared__ float Bs[8][128];

    const int z = blockIdx.z;
    const float* __restrict__ W = (z == 0) ? Wq : (z == 1) ? Wk : Wv;
    const int m0 = blockIdx.y * 128;
    const int n0 = blockIdx.x * 128;
    const int tid = threadIdx.x;
    const int tx = tid & 15;
    const int ty = tid >> 4;

    const int arow = tid >> 1;
    const int acol = (tid & 1) * 4;
    const int brow = tid >> 5;
    const int bcol = (tid & 31) * 4;

    float acc[8][8];
#pragma unroll
    for (int i = 0; i < 8; i++)
#pragma unroll
        for (int j = 0; j < 8; j++) acc[i][j] = 0.f;

    for (int k0 = 0; k0 < HH; k0 += 8) {
        float4 av = *(const float4*)&x[clamp4((m0 + arow) * HH + (k0 + acol), x_lim)];
        float4 bv = *(const float4*)&W[clamp4((k0 + brow) * HH + (n0 + bcol), w_lim)];
        __syncthreads();
        As[acol + 0][arow] = av.x;
        As[acol + 1][arow] = av.y;
        As[acol + 2][arow] = av.z;
        As[acol + 3][arow] = av.w;
        *(float4*)&Bs[brow][bcol] = bv;
        __syncthreads();
#pragma unroll
        for (int kk = 0; kk < 8; kk++) {
            float a[8], b[8];
            *(float4*)&a[0] = *(const float4*)&As[kk][ty * 4];
            *(float4*)&a[4] = *(const float4*)&As[kk][64 + ty * 4];
            *(float4*)&b[0] = *(const float4*)&Bs[kk][tx * 4];
            *(float4*)&b[4] = *(const float4*)&Bs[kk][64 + tx * 4];
#pragma unroll
            for (int i = 0; i < 8; i++)
#pragma unroll
                for (int j = 0; j < 8; j++)
                    acc[i][j] = fmaf(a[i], b[j], acc[i][j]);
        }
    }

#pragma unroll
    for (int i = 0; i < 8; i++) {
        const int m = m0 + ((i < 4) ? (ty * 4 + i) : (64 + ty * 4 + i - 4));
        const int s = m & (SS - 1);
        const float nf = (float)(s + 1);
#pragma unroll
        for (int jp = 0; jp < 4; jp++) {          // pairs (0,1)(2,3)(4,5)(6,7)
            const int je = jp * 2;
            const int n = n0 + ((je < 4) ? (tx * 4 + je) : (64 + tx * 4 + je - 4));
            const float v0 = acc[i][je], v1 = acc[i][je + 1];
            const int idx = m * HH + n;           // even; in range by construction
            if (z == 2) {
                store_split2(g_v_h, g_v_l, idx, v0, v1);
            } else {
                float sn0, cs0, sn1, cs1;
                sincosf(nf * theta[clamp1(n, th_lim)],     &sn0, &cs0);
                sincosf(nf * theta[clamp1(n + 1, th_lim)], &sn1, &cs1);
                if (z == 0) {
                    store_split2(g_qr_h, g_qr_l, idx, v0 * cs0, v1 * cs1);
                    store_split2(g_qi_h, g_qi_l, idx, v0 * sn0, v1 * sn1);
                } else {
                    store_split2(g_kr_h, g_kr_l, idx, v0 * cs0, v1 * cs1);
                    store_split2(g_ks_h, g_ks_l, idx, v0 * sn0, v1 * sn1);
                }
            }
        }
    }
}

// ============================================================================
// Kernel 2: REAL scores via mma.sync bf16 split.  Sr = qr*kr + qi*ks
// (ks = +v*sin, sign pre-flipped), then decay gamma^(i-j), stored split-bf16.
// CTA 128x128, 8 warps (2x4), warp 64x32, K=512 in k16 steps. Grid (16,16,4).
// ============================================================================
__global__ __launch_bounds__(256) void scores_kernel()
{
    const int j0 = blockIdx.x * 128;
    const int i0 = blockIdx.y * 128;
    if (j0 > i0 + 127) return;
    const int b = blockIdx.z;
    const int rbase = b * SS;

    // 4 A planes (qr_h, qr_l, qi_h, qi_l) and 4 B planes (kr_h, kr_l, ks_h, ks_l)
    __shared__ __nv_bfloat16 sA[4][128][24];    // 24 = 16 + 8 pad (48B stride, conflict-free)
    __shared__ __nv_bfloat16 sB[4][128][24];

    const int tid = threadIdx.x;
    const int w = tid >> 5, lane = tid & 31;
    const int wr = w >> 2, wc = w & 3;           // warp tile: i += 64*wr, j += 32*wc
    const int g = lane >> 2, t = lane & 3;

    const int lrow = tid >> 1, lk8 = (tid & 1) * 8;        // global->smem copy map
    const int ar = lane & 15, ac = (lane >> 4) * 8;        // ldmatrix A lane addr
    const int br = ((lane >> 4) << 3) + (lane & 7);        // ldmatrix B lane addr
    const int bc = ((lane >> 3) & 1) * 8;

    float C[4][4][4];                             // [m-tile][n-tile][frag]
#pragma unroll
    for (int a = 0; a < 4; a++)
#pragma unroll
        for (int nb = 0; nb < 4; nb++)
#pragma unroll
            for (int q = 0; q < 4; q++) C[a][nb][q] = 0.f;

    for (int k0 = 0; k0 < HH; k0 += 16) {
        __syncthreads();
        {
            const int go = (rbase + i0 + lrow) * HH + k0 + lk8;
            *(uint4*)&sA[0][lrow][lk8] = *(const uint4*)&g_qr_h[go];
            *(uint4*)&sA[1][lrow][lk8] = *(const uint4*)&g_qr_l[go];
            *(uint4*)&sA[2][lrow][lk8] = *(const uint4*)&g_qi_h[go];
            *(uint4*)&sA[3][lrow][lk8] = *(const uint4*)&g_qi_l[go];
            const int gb = (rbase + j0 + lrow) * HH + k0 + lk8;
            *(uint4*)&sB[0][lrow][lk8] = *(const uint4*)&g_kr_h[gb];
            *(uint4*)&sB[1][lrow][lk8] = *(const uint4*)&g_kr_l[gb];
            *(uint4*)&sB[2][lrow][lk8] = *(const uint4*)&g_ks_h[gb];
            *(uint4*)&sB[3][lrow][lk8] = *(const uint4*)&g_ks_l[gb];
        }
        __syncthreads();

#pragma unroll
        for (int pass = 0; pass < 2; pass++) {    // 0: qr*kr, 1: qi*ks
            const int pb = pass * 2;
            uint32_t Ah[4][4], Al[4][4], Bh[4][2], Bl[4][2];
#pragma unroll
            for (int a = 0; a < 4; a++) {
                ldsm_x4(Ah[a][0], Ah[a][1], Ah[a][2], Ah[a][3],
                        s2u(&sA[pb + 0][64 * wr + 16 * a + ar][ac]));
                ldsm_x4(Al[a][0], Al[a][1], Al[a][2], Al[a][3],
                        s2u(&sA[pb + 1][64 * wr + 16 * a + ar][ac]));
            }
#pragma unroll
            for (int p = 0; p < 2; p++) {
                uint32_t r0, r1, r2, r3;
                ldsm_x4(r0, r1, r2, r3, s2u(&sB[pb + 0][32 * wc + 16 * p + br][bc]));
                Bh[2 * p][0] = r0; Bh[2 * p][1] = r1;
                Bh[2 * p + 1][0] = r2; Bh[2 * p + 1][1] = r3;
                ldsm_x4(r0, r1, r2, r3, s2u(&sB[pb + 1][32 * wc + 16 * p + br][bc]));
                Bl[2 * p][0] = r0; Bl[2 * p][1] = r1;
                Bl[2 * p + 1][0] = r2; Bl[2 * p + 1][1] = r3;
            }
#pragma unroll
            for (int a = 0; a < 4; a++)
#pragma unroll
                for (int nb = 0; nb < 4; nb++) {
                    mma16816(C[a][nb], Ah[a], Bh[nb]);   // hi*hi
                    mma16816(C[a][nb], Ah[a], Bl[nb]);   // hi*lo
                    mma16816(C[a][nb], Al[a], Bh[nb]);   // lo*hi
                }
        }
    }

    // decay + split-bf16 store
    const int sbase = b * SS * SS;
#pragma unroll
    for (int a = 0; a < 4; a++) {
        const int ibase = i0 + 64 * wr + 16 * a;
#pragma unroll
        for (int nb = 0; nb < 4; nb++) {
            const int jb = j0 + 32 * wc + 8 * nb + 2 * t;
#pragma unroll
            for (int half = 0; half < 2; half++) {
                const int i = ibase + g + half * 8;
                float x0 = C[a][nb][half * 2 + 0];
                float x1 = C[a][nb][half * 2 + 1];
                const int d0 = i - jb, d1 = i - jb - 1;
                x0 *= (d0 < 0) ? 0.f : exp2f((float)d0 * LOG2_GAMMA);
                x1 *= (d1 < 0) ? 0.f : exp2f((float)d1 * LOG2_GAMMA);
                store_split2(g_sr_h, g_sr_l, sbase + i * SS + jb, x0, x1);
            }
        }
    }
}

// ============================================================================
// Kernel 3: O = Sr @ V via mma.sync bf16 split (triangular j < i0+128).
// CTA 128(i) x 64(h), 8 warps (2x4), warp 64x16. Grid (8, 16, 4).
// Output: real part, float32 [B,S,H].
// ============================================================================
__global__ __launch_bounds__(256) void out_kernel(float* __restrict__ out,
                                                  int out_limf)
{
    const int h0 = blockIdx.x * 64;
    const int i0 = blockIdx.y * 128;
    const int b  = blockIdx.z;
    const int sbase = b * SS * SS;
    const int rbase = b * SS;

    __shared__ __nv_bfloat16 sS[2][128][24];     // S hi/lo  [i][k16 + pad]
    __shared__ __nv_bfloat16 sV[2][16][72];      // V hi/lo  [k][64h + 8 pad] (144B stride)

    const int tid = threadIdx.x;
    const int w = tid >> 5, lane = tid & 31;
    const int wr = w >> 2, wc = w & 3;           // warp tile: i += 64*wr, h += 16*wc
    const int g = lane >> 2, t = lane & 3;

    const int lrow = tid >> 1, lk8 = (tid & 1) * 8;
    const int vrow = tid >> 3, vh8 = (tid & 7) * 8;        // V copy map (tid < 128)
    const int ar = lane & 15, ac = (lane >> 4) * 8;        // ldmatrix A
    const int vr_l = (lane & 7) + ((lane >> 3) & 1) * 8;   // ldmatrix V (.trans)
    const int vc_l = (lane >> 4) * 8;

    float C[4][2][4];
#pragma unroll
    for (int a = 0; a < 4; a++)
#pragma unroll
        for (int nb = 0; nb < 2; nb++)
#pragma unroll
            for (int q = 0; q < 4; q++) C[a][nb][q] = 0.f;

    const int jend = i0 + 128;
    for (int jl = 0; jl < jend; jl += 16) {
        __syncthreads();
        {
            const int go = sbase + (i0 + lrow) * SS + jl + lk8;
            *(uint4*)&sS[0][lrow][lk8] = *(const uint4*)&g_sr_h[go];
            *(uint4*)&sS[1][lrow][lk8] = *(const uint4*)&g_sr_l[go];
            if (tid < 128) {
                const int gv = (rbase + jl + vrow) * HH + h0 + vh8;
                *(uint4*)&sV[0][vrow][vh8] = *(const uint4*)&g_v_h[gv];
                *(uint4*)&sV[1][vrow][vh8] = *(const uint4*)&g_v_l[gv];
            }
        }
        __syncthreads();

        uint32_t Ah[4][4], Al[4][4], Bh[2][2], Bl[2][2];
#pragma unroll
        for (int a = 0; a < 4; a++) {
            ldsm_x4(Ah[a][0], Ah[a][1], Ah[a][2], Ah[a][3],
                    s2u(&sS[0][64 * wr + 16 * a + ar][ac]));
            ldsm_x4(Al[a][0], Al[a][1], Al[a][2], Al[a][3],
                    s2u(&sS[1][64 * wr + 16 * a + ar][ac]));
        }
        {
            uint32_t r0, r1, r2, r3;
            ldsm_x4_t(r0, r1, r2, r3, s2u(&sV[0][vr_l][16 * wc + vc_l]));
            Bh[0][0] = r0; Bh[0][1] = r1; Bh[1][0] = r2; Bh[1][1] = r3;
            ldsm_x4_t(r0, r1, r2, r3, s2u(&sV[1][vr_l][16 * wc + vc_l]));
            Bl[0][0] = r0; Bl[0][1] = r1; Bl[1][0] = r2; Bl[1][1] = r3;
        }
#pragma unroll
        for (int a = 0; a < 4; a++)
#pragma unroll
            for (int nb = 0; nb < 2; nb++) {
                mma16816(C[a][nb], Ah[a], Bh[nb]);   // hi*hi
                mma16816(C[a][nb], Ah[a], Bl[nb]);   // hi*lo
                mma16816(C[a][nb], Al[a], Bh[nb]);   // lo*hi
            }
    }

#pragma unroll
    for (int a = 0; a < 4; a++) {
        const int ibase = i0 + 64 * wr + 16 * a;
#pragma unroll
        for (int nb = 0; nb < 2; nb++) {
            const int h = h0 + 16 * wc + 8 * nb + 2 * t;
#pragma unroll
            for (int half = 0; half < 2; half++) {
                const int gi = ibase + g + half * 8;
                const int o0 = (rbase + gi) * HH + h;
                out[clamp1(o0,     out_limf)] = C[a][nb][half * 2 + 0];
                out[clamp1(o0 + 1, out_limf)] = C[a][nb][half * 2 + 1];
            }
        }
    }
}

// ============================================================================
// Binding (rank by size, order/unit-independent, null fallbacks) + runtime
// extents. Output: float32 real part, min(out_size, QKV_LIM) floats.
// ============================================================================
extern "C" void kernel_launch(void* const* d_in, const int* in_sizes, int n_in,
                              void* d_out, int out_size)
{
    long long smax = -1, smin = 0x7fffffffffffLL;
    for (int i = 0; i < n_in; i++) {
        long long s = (long long)in_sizes[i];
        if (s > smax) smax = s;
        if (s < smin) smin = s;
    }

    const float* x  = nullptr;
    const float* th = nullptr;
    const float* wbuf[3] = {nullptr, nullptr, nullptr};
    long long xs = QKV_LIM, ths = HH, ws = W_LIM;
    int nw = 0;
    int x_pos = -1, th_pos = 1 << 30;

    for (int i = 0; i < n_in; i++) {
        long long s = (long long)in_sizes[i];
        if (s == smax && x == nullptr)       { x  = (const float*)d_in[i]; xs = s;  x_pos  = i; }
        else if (s == smin && th == nullptr) { th = (const float*)d_in[i]; ths = s; th_pos = i; }
        else if (nw < 3)                     { ws = s; wbuf[nw++] = (const float*)d_in[i]; }
    }

    const float* safe = (const float*)d_in[0];
    if (!x)  x  = safe;
    if (!th) th = safe;
    for (int i = 0; i < 3; i++) if (!wbuf[i]) wbuf[i] = safe;

    const float *wq, *wk, *wv;
    if (x_pos < th_pos) {            // dict order: x, wq, wk, wv, theta
        wq = wbuf[0]; wk = wbuf[1]; wv = wbuf[2];
    } else {                         // alphabetical: theta, wk, wq, wv, x
        wk = wbuf[0]; wq = wbuf[1]; wv = wbuf[2];
    }

    int x_lim  = (int)((xs  < (long long)QKV_LIM) ? xs  : QKV_LIM);
    int w_lim  = (int)((ws  < (long long)W_LIM)   ? ws  : W_LIM);
    int th_lim = (int)((ths < (long long)HH)      ? ths : HH);
    if (x_lim < 4)  x_lim = 4;
    if (w_lim < 4)  w_lim = 4;
    if (th_lim < 1) th_lim = 1;

    long long o = (long long)out_size;
    long long out_limf = (o < (long long)QKV_LIM) ? o : (long long)QKV_LIM;
    if (out_limf < 1) out_limf = 1;

    qkv_kernel<<<dim3(HH / 128, NROWS / 128, 3), 256>>>(x, wq, wk, wv, th,
                                                        x_lim, w_lim, th_lim);
    scores_kernel<<<dim3(SS / 128, SS / 128, BB), 256>>>();
    out_kernel<<<dim3(HH / 64, SS / 128, BB), 256>>>((float*)d_out, (int)out_limf);
}